// round 12
// baseline (speedup 1.0000x reference)
#include <cuda_runtime.h>
#include <cstdint>

// Cost-volume correlation, MAX_DISP=4 (81 disps), kernel_size=1.
// out[b, dy*9+dx, y, x] = (1/C) * sum_c in1[b,c,y,x] * in2[b,c,y+dy-4,x+dx-4]
//
// R12: 8 pixels/thread (block 16x8, full-width row), one dy per block.
// Window = 16 floats = 4 LDS.128 per thread-channel (vs 6 per 8px before).
// 72 acc regs (20 u64 even-dx pairs + 32 scalar odd-dx); launch_bounds(128,4)
// -> 4 CTAs/SM. Per-warp cp.async pipelines (warp stages its two y-rows),
// __syncwarp only. Channel loop unrolled x4 so ring offsets are constants.

typedef unsigned long long u64;

__device__ __forceinline__ void fma2(u64 &d, u64 a, u64 b) {
    asm("fma.rn.f32x2 %0, %1, %2, %0;" : "+l"(d) : "l"(a), "l"(b));
}
__device__ __forceinline__ u64 pk(float lo, float hi) {
    u64 r; asm("mov.b64 %0, {%1,%2};" : "=l"(r) : "f"(lo), "f"(hi)); return r;
}
__device__ __forceinline__ void upk(u64 v, float &lo, float &hi) {
    asm("mov.b64 {%0,%1}, %2;" : "=f"(lo), "=f"(hi) : "l"(v));
}
__device__ __forceinline__ void cpasync16(uint32_t d, const float* s) {
    asm volatile("cp.async.cg.shared.global [%0], [%1], 16;" :: "r"(d), "l"(s));
}

#define CC 128
#define HH 128
#define WW 128
#define HW (HH * WW)
#define NDISP 81
#define TILE_C 136                   // 128 px + 8 halo (floats per row)
#define ROW_F TILE_C
#define ROW_B (TILE_C * 4)           // 544 B
#define STAGE_F (8 * TILE_C)         // 8 rows per stage
#define STAGE_B (STAGE_F * 4)        // 4352 B
#define STAGES 4

__global__ __launch_bounds__(128, 4)
void corr_kernel(const float* __restrict__ in1,
                 const float* __restrict__ in2,
                 float* __restrict__ out)
{
    __shared__ __align__(16) float sm[STAGES * STAGE_F];

    const int tx = threadIdx.x;              // 0..15
    const int ty = threadIdx.y;              // 0..7  (y row = smem row)
    const int dy = blockIdx.x;               // 0..8
    const int y0 = blockIdx.y * 8;
    const int b  = blockIdx.z;

    const int y = y0 + ty;
    const int x = tx * 8;                    // pixels x..x+7

    const float* i1 = in1 + ((b * CC) * HH + y) * WW + x;

    // ---- per-warp staging: warp covers rows rowA = ty&~1 and rowA+1 ----
    const int lane = ((ty & 1) << 4) | tx;   // 0..31
    const int rowA = ty & ~1;
    const int rowB = rowA + 1;
    const int gyA  = y0 + rowA + dy - 4;
    const int gyB  = gyA + 1;
    const bool rAok = (gyA >= 0) && (gyA < HH);
    const bool rBok = (gyB >= 0) && (gyB < HH);

    // quad q of a row covers gx = 4q-4 .. 4q-1 (q=0..33; q=0 and q=33 are x-OOB)
    const float* i2b = in2 + (b * CC) * HW;
    const float* sA = i2b + gyA * WW + (4 * lane - 4);   // main quad q = lane
    const float* sB = i2b + gyB * WW + (4 * lane - 4);
    const uint32_t smb = (uint32_t)__cvta_generic_to_shared(sm);
    const uint32_t dA = smb + rowA * ROW_B + lane * 16;
    const uint32_t dB = smb + rowB * ROW_B + lane * 16;
    const bool okA = (lane >= 1) && rAok;
    const bool okB = (lane >= 1) && rBok;
    const bool eA  = (lane == 0) && rAok;    // extra quad q=32 (gx 124..127)
    const bool eB  = (lane == 0) && rBok;
    const uint32_t dAe = dA + 32 * 16;
    const uint32_t dBe = dB + 32 * 16;

    // zero never-written (OOB) quads once, all stages
    {
        float4 z = make_float4(0.f, 0.f, 0.f, 0.f);
        float* rA = sm + rowA * ROW_F;
        float* rB = sm + rowB * ROW_F;
#pragma unroll
        for (int s = 0; s < STAGES; s++) {
            if (!okA) *(float4*)(rA + s * STAGE_F + lane * 4) = z;
            if (!okB) *(float4*)(rB + s * STAGE_F + lane * 4) = z;
            if (lane == 0 && !rAok) *(float4*)(rA + s * STAGE_F + 128) = z;
            if (lane == 0 && !rBok) *(float4*)(rB + s * STAGE_F + 128) = z;
            if (lane == 1) {                 // q=33 always x-OOB
                *(float4*)(rA + s * STAGE_F + 132) = z;
                *(float4*)(rB + s * STAGE_F + 132) = z;
            }
        }
    }

    // Prologue: channels 0..2 into stages 0..2.
#pragma unroll
    for (int c = 0; c < 3; c++) {
        const uint32_t o = c * STAGE_B;
        if (okA) cpasync16(dA + o, sA + c * HW);
        if (okB) cpasync16(dB + o, sB + c * HW);
        if (eA)  cpasync16(dAe + o, sA + 128 + c * HW);
        if (eB)  cpasync16(dBe + o, sB + 128 + c * HW);
        asm volatile("cp.async.commit_group;");
    }
    float4 aqa0 = *(const float4*)i1;
    float4 aqb0 = *(const float4*)(i1 + 4);
    float4 aqa1 = *(const float4*)(i1 + HW);
    float4 aqb1 = *(const float4*)(i1 + HW + 4);

    const float* i1n = i1 + 2 * HW;          // in1 channel c+2
    const float* sAn = sA + 3 * HW;          // in2 channel c+3
    const float* sBn = sB + 3 * HW;
    const float* smrow = sm + ty * ROW_F + x;  // window col0 (gx=x-4), stage 0

    u64   accE[20];   // even dx=2k, px pair j: accE[k*4+j] covers px (2j,2j+1)
    float accO[32];   // odd dx=2t+1, px p: accO[t*8+p]
#pragma unroll
    for (int i = 0; i < 20; i++) accE[i] = 0ull;
#pragma unroll
    for (int i = 0; i < 32; i++) accO[i] = 0.f;

    for (int c4 = 0; c4 < CC; c4 += 4) {
#pragma unroll
        for (int u = 0; u < 4; u++) {
            const int c = c4 + u;
            asm volatile("cp.async.wait_group 2;" ::: "memory");
            __syncwarp();

            float4 na = make_float4(0.f, 0.f, 0.f, 0.f), nb = na;
            if (c + 2 < CC) {
                na = *(const float4*)i1n;
                nb = *(const float4*)(i1n + 4);
                i1n += HW;
            }
            if (c + 3 < CC) {
                const uint32_t o = ((u + 3) & 3) * STAGE_B;
                if (okA) cpasync16(dA + o, sAn);
                if (okB) cpasync16(dB + o, sBn);
                if (eA)  cpasync16(dAe + o, sAn + 128);
                if (eB)  cpasync16(dBe + o, sBn + 128);
                sAn += HW; sBn += HW;
            }
            asm volatile("cp.async.commit_group;");

            // window w[0..15] = gx x-4..x+11 ; P[i] = packed (w[2i], w[2i+1])
            const ulonglong2* W = (const ulonglong2*)(smrow + u * STAGE_F);
            ulonglong2 Q0 = W[0], Q1 = W[1], Q2 = W[2], Q3 = W[3];
            const u64 P0 = Q0.x, P1 = Q0.y, P2 = Q1.x, P3 = Q1.y;
            const u64 P4 = Q2.x, P5 = Q2.y, P6 = Q3.x, P7 = Q3.y;

            const u64 A0 = pk(aqa0.x, aqa0.y), A1 = pk(aqa0.z, aqa0.w);
            const u64 A2 = pk(aqb0.x, aqb0.y), A3 = pk(aqb0.z, aqb0.w);

            // even dx = 2k: accE[k*4+j] += A_j * P[k+j]
            fma2(accE[ 0], A0, P0); fma2(accE[ 1], A1, P1); fma2(accE[ 2], A2, P2); fma2(accE[ 3], A3, P3);
            fma2(accE[ 4], A0, P1); fma2(accE[ 5], A1, P2); fma2(accE[ 6], A2, P3); fma2(accE[ 7], A3, P4);
            fma2(accE[ 8], A0, P2); fma2(accE[ 9], A1, P3); fma2(accE[10], A2, P4); fma2(accE[11], A3, P5);
            fma2(accE[12], A0, P3); fma2(accE[13], A1, P4); fma2(accE[14], A2, P5); fma2(accE[15], A3, P6);
            fma2(accE[16], A0, P4); fma2(accE[17], A1, P5); fma2(accE[18], A2, P6); fma2(accE[19], A3, P7);

            // odd dx = 2t+1 via register halves: operand(px p) = w[p+2t+1]
            float l0,h0,l1,h1,l2,h2,l3,h3,l4,h4,l5,h5,l6,h6,l7,h7;
            upk(P0,l0,h0); upk(P1,l1,h1); upk(P2,l2,h2); upk(P3,l3,h3);
            upk(P4,l4,h4); upk(P5,l5,h5); upk(P6,l6,h6); upk(P7,l7,h7);
            const float a0 = aqa0.x, a1 = aqa0.y, a2 = aqa0.z, a3 = aqa0.w;
            const float a4 = aqb0.x, a5 = aqb0.y, a6 = aqb0.z, a7 = aqb0.w;
            // t=0
            accO[ 0] = fmaf(a0, h0, accO[ 0]);
            accO[ 1] = fmaf(a1, l1, accO[ 1]);
            accO[ 2] = fmaf(a2, h1, accO[ 2]);
            accO[ 3] = fmaf(a3, l2, accO[ 3]);
            accO[ 4] = fmaf(a4, h2, accO[ 4]);
            accO[ 5] = fmaf(a5, l3, accO[ 5]);
            accO[ 6] = fmaf(a6, h3, accO[ 6]);
            accO[ 7] = fmaf(a7, l4, accO[ 7]);
            // t=1
            accO[ 8] = fmaf(a0, h1, accO[ 8]);
            accO[ 9] = fmaf(a1, l2, accO[ 9]);
            accO[10] = fmaf(a2, h2, accO[10]);
            accO[11] = fmaf(a3, l3, accO[11]);
            accO[12] = fmaf(a4, h3, accO[12]);
            accO[13] = fmaf(a5, l4, accO[13]);
            accO[14] = fmaf(a6, h4, accO[14]);
            accO[15] = fmaf(a7, l5, accO[15]);
            // t=2
            accO[16] = fmaf(a0, h2, accO[16]);
            accO[17] = fmaf(a1, l3, accO[17]);
            accO[18] = fmaf(a2, h3, accO[18]);
            accO[19] = fmaf(a3, l4, accO[19]);
            accO[20] = fmaf(a4, h4, accO[20]);
            accO[21] = fmaf(a5, l5, accO[21]);
            accO[22] = fmaf(a6, h5, accO[22]);
            accO[23] = fmaf(a7, l6, accO[23]);
            // t=3
            accO[24] = fmaf(a0, h3, accO[24]);
            accO[25] = fmaf(a1, l4, accO[25]);
            accO[26] = fmaf(a2, h4, accO[26]);
            accO[27] = fmaf(a3, l5, accO[27]);
            accO[28] = fmaf(a4, h5, accO[28]);
            accO[29] = fmaf(a5, l6, accO[29]);
            accO[30] = fmaf(a6, h6, accO[30]);
            accO[31] = fmaf(a7, l7, accO[31]);

            aqa0 = aqa1; aqb0 = aqb1;
            aqa1 = na;   aqb1 = nb;
        }
    }

    // ---- epilogue: mean over C, float4 stores ----
    const float s = 1.0f / (float)CC;
    float* ob = out + ((b * NDISP + dy * 9) * HH + y) * WW + x;
#pragma unroll
    for (int k = 0; k < 5; k++) {            // even dx = 2k
        float e0,e1,e2,e3,e4,e5,e6,e7;
        upk(accE[k*4+0], e0, e1);
        upk(accE[k*4+1], e2, e3);
        upk(accE[k*4+2], e4, e5);
        upk(accE[k*4+3], e6, e7);
        *(float4*)(ob + 2*k*HW)     = make_float4(e0*s, e1*s, e2*s, e3*s);
        *(float4*)(ob + 2*k*HW + 4) = make_float4(e4*s, e5*s, e6*s, e7*s);
    }
#pragma unroll
    for (int t = 0; t < 4; t++) {            // odd dx = 2t+1
        float* p = ob + (2*t+1)*HW;
        *(float4*)p       = make_float4(accO[t*8+0]*s, accO[t*8+1]*s,
                                        accO[t*8+2]*s, accO[t*8+3]*s);
        *(float4*)(p + 4) = make_float4(accO[t*8+4]*s, accO[t*8+5]*s,
                                        accO[t*8+6]*s, accO[t*8+7]*s);
    }
}

extern "C" void kernel_launch(void* const* d_in, const int* in_sizes, int n_in,
                              void* d_out, int out_size)
{
    const float* in1 = (const float*)d_in[0];
    const float* in2 = (const float*)d_in[1];
    float* out = (float*)d_out;

    const int B = in_sizes[0] / (CC * HH * WW);   // 8

    dim3 block(16, 8);
    dim3 grid(9, HH / 8, B);
    corr_kernel<<<grid, block>>>(in1, in2, out);
}